// round 6
// baseline (speedup 1.0000x reference)
#include <cuda_runtime.h>
#include <cuda_bf16.h>

typedef unsigned long long ull;

#define TT 4
#define BB 2
#define NW 64
#define WS 128
#define CC 256
#define HH 8
#define HD 32
#define NQKV 768

// ---------------- scratch (device globals; no allocation allowed) -------------
__device__ float    g_region[BB * NW * CC];                    // 128 KB
__device__ int      g_idx[BB * NW * 4];
__device__ unsigned g_qbits[TT * BB * NW * WS * HH];           // 2 MB  [t,b,n,s,h] bit=d
__device__ unsigned g_kbits[TT * BB * NW * HH * HD * 4];       // 8 MB  [t,b,n,h,d,w] bit=s%32
__device__ unsigned g_vbits[TT * BB * NW * HH * HD * 4];       // 8 MB
__device__ float    g_attn[TT * BB * NW * WS * CC];            // 64 MB [row][256]

// (t,b,n,s) -> element offset of the row in x / out  (windowize mapping)
__device__ __forceinline__ int win_row_off(int t, int b, int n, int s) {
    int iwt = n >> 4, iwh = (n >> 2) & 3, iww = n & 3;
    int ipt = s >> 6, iph = (s >> 3) & 7, ipw = s & 7;
    int lt = iwt * 2 + ipt;
    int lh = iwh * 8 + iph;
    int lw = iww * 8 + ipw;
    return ((((t * BB + b) * 8 + lt) * 32 + lh) * 32 + lw) * CC;
}

// ---- packed f32x2 helpers (Blackwell FFMA2: 2 FMAs per issue) ----------------
__device__ __forceinline__ ull dupf(float a) {
    ull r; unsigned u = __float_as_uint(a);
    asm("mov.b64 %0, {%1, %1};" : "=l"(r) : "r"(u));
    return r;
}
__device__ __forceinline__ void fma2(ull& d, ull a, ull b) {
    asm("fma.rn.f32x2 %0, %1, %2, %0;" : "+l"(d) : "l"(a), "l"(b));
}
__device__ __forceinline__ float lo32(ull v) { return __uint_as_float((unsigned)v); }
__device__ __forceinline__ float hi32(ull v) { return __uint_as_float((unsigned)(v >> 32)); }

// ---------------- 1) region sums --------------------------------------------
__global__ void region_kernel(const float* __restrict__ x) {
    int b = blockIdx.x >> 6, n = blockIdx.x & 63;
    int c = threadIdx.x;
    float acc = 0.f;
    for (int t = 0; t < TT; ++t) {
#pragma unroll 8
        for (int s = 0; s < WS; ++s)
            acc += x[win_row_off(t, b, n, s) + c];
    }
    g_region[(b * NW + n) * CC + c] = acc;   // positive scales dropped (rank-only use)
}

// ---------------- 2) scores + top-4 -----------------------------------------
__global__ void topk_kernel() {
    int b = blockIdx.x;
    __shared__ float sc[64][65];
    int tid = threadIdx.x;
    for (int p = tid; p < 64 * 64; p += 256) {
        int i = p >> 6, j = p & 63;
        const float4* ri = (const float4*)&g_region[(b * NW + i) * CC];
        const float4* rj = (const float4*)&g_region[(b * NW + j) * CC];
        float a0 = 0.f, a1 = 0.f, a2 = 0.f, a3 = 0.f;
#pragma unroll 8
        for (int c = 0; c < CC / 4; ++c) {
            float4 u = ri[c], w = rj[c];
            a0 += u.x * w.x; a1 += u.y * w.y; a2 += u.z * w.z; a3 += u.w * w.w;
        }
        sc[i][j] = (a0 + a1) + (a2 + a3);
    }
    __syncthreads();
    if (tid < 64) {
        ull chosen = 0;
        for (int p = 0; p < 4; ++p) {
            float best = -1e30f; int bj = 0;
            for (int j = 0; j < 64; ++j) {
                if (!((chosen >> j) & 1ULL) && sc[tid][j] > best) { best = sc[tid][j]; bj = j; }
            }
            chosen |= 1ULL << bj;
            g_idx[(b * NW + tid) * 4 + p] = bj;
        }
    }
}

// ---------------- 3) QKV GEMM (fp32, f32x2) + LIF + bitpack ------------------
__global__ __launch_bounds__(256, 2)
void qkv_kernel(const float* __restrict__ x, const float* __restrict__ Wqkv,
                const float* __restrict__ bqkv) {
    int tbn = blockIdx.x;
    int t = tbn >> 7, b = (tbn >> 6) & 1, n = tbn & 63;
    int ntile = blockIdx.y * 128;

    __shared__ __align__(16) float s_As[128 * 36];   // [m][k] pad 36
    __shared__ __align__(16) float s_Bs[32 * 132];   // [k][n] pad 132
    __shared__ int rowoff[128];

    int tid = threadIdx.x;
    int tx = tid & 15, ty = tid >> 4;
    int m0 = ty * 8, n0 = tx * 8;

    if (tid < 128) rowoff[tid] = win_row_off(t, b, n, tid);
    __syncthreads();

    ull acc[8][4];
#pragma unroll
    for (int i = 0; i < 8; ++i)
#pragma unroll
        for (int p = 0; p < 4; ++p) acc[i][p] = 0ULL;

    for (int kt = 0; kt < CC; kt += 32) {
#pragma unroll
        for (int i = 0; i < 4; ++i) {
            int lin = tid + 256 * i;
            int r = lin >> 3, kq = lin & 7;
            float4 v = *(const float4*)(x + rowoff[r] + kt + kq * 4);
            *(float4*)&s_As[r * 36 + kq * 4] = v;
        }
#pragma unroll
        for (int i = 0; i < 4; ++i) {
            int lin = tid + 256 * i;
            int kk = lin >> 5, nq = lin & 31;
            float4 v = *(const float4*)(Wqkv + (kt + kk) * NQKV + ntile + nq * 4);
            *(float4*)&s_Bs[kk * 132 + nq * 4] = v;
        }
        __syncthreads();
#pragma unroll
        for (int k4 = 0; k4 < 8; ++k4) {
            float4 a4[8];
#pragma unroll
            for (int i = 0; i < 8; ++i)
                a4[i] = *(const float4*)&s_As[(m0 + i) * 36 + k4 * 4];
#pragma unroll
            for (int kk = 0; kk < 4; ++kk) {
                ulonglong2 bA = *(const ulonglong2*)&s_Bs[(k4 * 4 + kk) * 132 + n0];
                ulonglong2 bB = *(const ulonglong2*)&s_Bs[(k4 * 4 + kk) * 132 + n0 + 4];
#pragma unroll
                for (int i = 0; i < 8; ++i) {
                    float av = (kk == 0) ? a4[i].x : (kk == 1) ? a4[i].y
                             : (kk == 2) ? a4[i].z : a4[i].w;
                    ull ap = dupf(av);
                    fma2(acc[i][0], ap, bA.x);
                    fma2(acc[i][1], ap, bA.y);
                    fma2(acc[i][2], ap, bB.x);
                    fma2(acc[i][3], ap, bB.y);
                }
            }
        }
        __syncthreads();
    }

    // epilogue: bias + LIF threshold -> byte tile (alias As)
    unsigned char* Sbyte = (unsigned char*)s_As;   // 128*128 bytes
    float4 bv0 = *(const float4*)(bqkv + ntile + n0);
    float4 bv1 = *(const float4*)(bqkv + ntile + n0 + 4);
    float bias[8] = { bv0.x, bv0.y, bv0.z, bv0.w, bv1.x, bv1.y, bv1.z, bv1.w };
#pragma unroll
    for (int i = 0; i < 8; ++i) {
#pragma unroll
        for (int p = 0; p < 4; ++p) {
            float f0 = lo32(acc[i][p]) + bias[2 * p];
            float f1 = hi32(acc[i][p]) + bias[2 * p + 1];
            Sbyte[(m0 + i) * 128 + n0 + 2 * p]     = (f0 >= 2.0f) ? 1 : 0;
            Sbyte[(m0 + i) * 128 + n0 + 2 * p + 1] = (f1 >= 2.0f) ? 1 : 0;
        }
    }
    __syncthreads();

    int type = ntile >> 8;          // 0=q 1=k 2=v
    int colbase = ntile & 255;      // 0 or 128
    if (type == 0) {
        for (int w = tid; w < 512; w += 256) {
            int m = w >> 2, hh = w & 3;
            unsigned bits = 0;
#pragma unroll
            for (int d = 0; d < 32; ++d)
                bits |= ((unsigned)Sbyte[m * 128 + hh * 32 + d]) << d;
            int h = (colbase >> 5) + hh;
            g_qbits[(((t * BB + b) * NW + n) * WS + m) * HH + h] = bits;
        }
    } else {
        unsigned* dst = (type == 1) ? g_kbits : g_vbits;
        for (int w = tid; w < 512; w += 256) {
            int nl = w >> 2, sw = w & 3;
            unsigned bits = 0;
#pragma unroll
            for (int j = 0; j < 32; ++j)
                bits |= ((unsigned)Sbyte[(sw * 32 + j) * 128 + nl]) << j;
            int col = colbase + nl;
            int h = col >> 5, d = col & 31;
            dst[((((t * BB + b) * NW + n) * HH + h) * HD + d) * 4 + sw] = bits;
        }
    }
}

// ---------------- 4) linear attention over bit-packed spikes -----------------
__global__ void attn_kernel() {
    int g = blockIdx.x;                        // ((t*B+b)*NW+n)*HH+h
    int h = g & 7, n = (g >> 3) & 63, b = (g >> 9) & 1, t = g >> 10;
    int tid = threadIdx.x;

    __shared__ unsigned kb[4 * 32 * 4];
    __shared__ unsigned vb[4 * 32 * 4];
    __shared__ unsigned short kvs[32][32];
    __shared__ unsigned short ks[32];
    __shared__ int widx[4];

    if (tid < 4) widx[tid] = g_idx[(b * NW + n) * 4 + tid];
    __syncthreads();

    for (int i = tid; i < 512; i += 256) {
        int win = i >> 7, r = i & 127;
        int base = (((t * BB + b) * NW + widx[win]) * HH + h) * 128;
        kb[win * 128 + r] = g_kbits[base + r];
        vb[win * 128 + r] = g_vbits[base + r];
    }
    __syncthreads();

    for (int p = tid; p < 1024; p += 256) {
        int d = p >> 5, e = p & 31;
        int s = 0;
#pragma unroll
        for (int win = 0; win < 4; ++win)
#pragma unroll
            for (int w = 0; w < 4; ++w)
                s += __popc(kb[win * 128 + d * 4 + w] & vb[win * 128 + e * 4 + w]);
        kvs[d][e] = (unsigned short)s;
    }
    if (tid < 32) {
        int d = tid, s = 0;
#pragma unroll
        for (int win = 0; win < 4; ++win)
#pragma unroll
            for (int w = 0; w < 4; ++w)
                s += __popc(kb[win * 128 + d * 4 + w]);
        ks[d] = (unsigned short)s;
    }
    __syncthreads();

    int s_ = tid & 127, half = tid >> 7;
    unsigned qm = g_qbits[(((t * BB + b) * NW + n) * WS + s_) * HH + h];
    float D = 0.f;
    {
        unsigned m = qm;
        while (m) { int d = __ffs(m) - 1; m &= m - 1; D += (float)ks[d]; }
    }
    float Dp = D + 1e-6f;
    int orow = ((((t * BB + b) * NW + n) * WS + s_) * CC) + h * HD + half * 16;
#pragma unroll
    for (int e = 0; e < 16; ++e) {
        int ee = half * 16 + e;
        float num = 0.f;
        unsigned m = qm;
        while (m) { int d = __ffs(m) - 1; m &= m - 1; num += (float)kvs[d][ee]; }
        g_attn[orow + e] = num / Dp;
    }
}

// ---------------- 5) proj GEMM + un-windowize store --------------------------
__global__ __launch_bounds__(256, 2)
void proj_kernel(const float* __restrict__ Wp, const float* __restrict__ bp,
                 float* __restrict__ out) {
    int tbn = blockIdx.x;
    int t = tbn >> 7, b = (tbn >> 6) & 1, n = tbn & 63;
    int ntile = blockIdx.y * 128;
    const float* A = g_attn + (size_t)tbn * WS * CC;

    __shared__ __align__(16) float s_As[128 * 36];
    __shared__ __align__(16) float s_Bs[32 * 132];
    __shared__ int ooff[128];

    int tid = threadIdx.x;
    int tx = tid & 15, ty = tid >> 4;
    int m0 = ty * 8, n0 = tx * 8;

    if (tid < 128) ooff[tid] = win_row_off(t, b, n, tid);
    __syncthreads();

    ull acc[8][4];
#pragma unroll
    for (int i = 0; i < 8; ++i)
#pragma unroll
        for (int p = 0; p < 4; ++p) acc[i][p] = 0ULL;

    for (int kt = 0; kt < CC; kt += 32) {
#pragma unroll
        for (int i = 0; i < 4; ++i) {
            int lin = tid + 256 * i;
            int r = lin >> 3, kq = lin & 7;
            float4 v = *(const float4*)(A + r * CC + kt + kq * 4);
            *(float4*)&s_As[r * 36 + kq * 4] = v;
        }
#pragma unroll
        for (int i = 0; i < 4; ++i) {
            int lin = tid + 256 * i;
            int kk = lin >> 5, nq = lin & 31;
            float4 v = *(const float4*)(Wp + (kt + kk) * CC + ntile + nq * 4);
            *(float4*)&s_Bs[kk * 132 + nq * 4] = v;
        }
        __syncthreads();
#pragma unroll
        for (int k4 = 0; k4 < 8; ++k4) {
            float4 a4[8];
#pragma unroll
            for (int i = 0; i < 8; ++i)
                a4[i] = *(const float4*)&s_As[(m0 + i) * 36 + k4 * 4];
#pragma unroll
            for (int kk = 0; kk < 4; ++kk) {
                ulonglong2 bA = *(const ulonglong2*)&s_Bs[(k4 * 4 + kk) * 132 + n0];
                ulonglong2 bB = *(const ulonglong2*)&s_Bs[(k4 * 4 + kk) * 132 + n0 + 4];
#pragma unroll
                for (int i = 0; i < 8; ++i) {
                    float av = (kk == 0) ? a4[i].x : (kk == 1) ? a4[i].y
                             : (kk == 2) ? a4[i].z : a4[i].w;
                    ull ap = dupf(av);
                    fma2(acc[i][0], ap, bA.x);
                    fma2(acc[i][1], ap, bA.y);
                    fma2(acc[i][2], ap, bB.x);
                    fma2(acc[i][3], ap, bB.y);
                }
            }
        }
        __syncthreads();
    }

    float4 bv0 = *(const float4*)(bp + ntile + n0);
    float4 bv1 = *(const float4*)(bp + ntile + n0 + 4);
#pragma unroll
    for (int i = 0; i < 8; ++i) {
        float4 o0, o1;
        o0.x = lo32(acc[i][0]) + bv0.x;  o0.y = hi32(acc[i][0]) + bv0.y;
        o0.z = lo32(acc[i][1]) + bv0.z;  o0.w = hi32(acc[i][1]) + bv0.w;
        o1.x = lo32(acc[i][2]) + bv1.x;  o1.y = hi32(acc[i][2]) + bv1.y;
        o1.z = lo32(acc[i][3]) + bv1.z;  o1.w = hi32(acc[i][3]) + bv1.w;
        int ro = ooff[m0 + i] + ntile + n0;
        *(float4*)(out + ro)     = o0;
        *(float4*)(out + ro + 4) = o1;
    }
}

// ---------------------------------------------------------------------------
extern "C" void kernel_launch(void* const* d_in, const int* in_sizes, int n_in,
                              void* d_out, int out_size) {
    const float* x     = (const float*)d_in[0];
    const float* Wqkv  = (const float*)d_in[1];
    const float* bqkv  = (const float*)d_in[2];
    const float* Wproj = (const float*)d_in[3];
    const float* bproj = (const float*)d_in[4];
    float* out = (float*)d_out;

    region_kernel<<<BB * NW, 256>>>(x);
    topk_kernel<<<BB, 256>>>();
    qkv_kernel<<<dim3(TT * BB * NW, 6), 256>>>(x, Wqkv, bqkv);
    attn_kernel<<<TT * BB * NW * HH, 256>>>();
    proj_kernel<<<dim3(TT * BB * NW, 2), 256>>>(Wproj, bproj, out);
}